// round 1
// baseline (speedup 1.0000x reference)
#include <cuda_runtime.h>
#include <cuda_bf16.h>
#include <math.h>

#define N_NODES 10000
#define N_EDGES 80000
#define EMB_DIM 128
#define IN_CH 64          // other_feats has IN_CH-1 = 63
#define IN_GNN 191
#define C1 2048
#define C2 1024
#define C3 1024
#define NUM_GRAPHS 16
#define H3 512
#define NUM_CLASSES 2

// ---------------- scratch (device globals; no runtime allocation) ------------
__device__ float d_x[N_NODES * IN_GNN];          // 7.6 MB
__device__ float d_h[N_NODES * C1];              // 81.9 MB
__device__ float d_agg[N_NODES * C1];            // 81.9 MB
__device__ float d_dinv[N_NODES];
__device__ int   d_cnt[N_NODES];                 // in-degree (real edges only)
__device__ int   d_rowptr[N_NODES + 1];
__device__ int   d_wofs[N_NODES];
__device__ int   d_colidx[N_EDGES];
__device__ float d_eval[N_EDGES];
__device__ float d_pool[NUM_GRAPHS * C3];
__device__ float d_gcnt[NUM_GRAPHS];
__device__ float d_m1[NUM_GRAPHS * 1024];
__device__ float d_m2[NUM_GRAPHS * 1024];
__device__ float d_m3[NUM_GRAPHS * H3];

// ---------------- small setup kernels ----------------------------------------
__global__ void init_kernel() {
    int i = blockIdx.x * blockDim.x + threadIdx.x;
    int total = N_NODES + NUM_GRAPHS * C3 + NUM_GRAPHS;
    for (; i < total; i += gridDim.x * blockDim.x) {
        if (i < N_NODES) d_cnt[i] = 0;
        else if (i < N_NODES + NUM_GRAPHS * C3) d_pool[i - N_NODES] = 0.0f;
        else d_gcnt[i - N_NODES - NUM_GRAPHS * C3] = 0.0f;
    }
}

__global__ void count_kernel(const int* __restrict__ edge_index) {
    int e = blockIdx.x * blockDim.x + threadIdx.x;
    if (e < N_EDGES) atomicAdd(&d_cnt[edge_index[N_EDGES + e]], 1);
}

__global__ void dinv_kernel() {
    int i = blockIdx.x * blockDim.x + threadIdx.x;
    if (i < N_NODES) d_dinv[i] = rsqrtf((float)(d_cnt[i] + 1));  // +1 self loop
}

__global__ void scan_kernel() {
    __shared__ int ps[1024];
    const int CH = (N_NODES + 1023) / 1024;  // 10
    int tid = threadIdx.x;
    int base = tid * CH;
    int s = 0;
    for (int k = 0; k < CH; k++) {
        int i = base + k;
        if (i < N_NODES) s += d_cnt[i];
    }
    ps[tid] = s;
    __syncthreads();
    for (int off = 1; off < 1024; off <<= 1) {
        int v = (tid >= off) ? ps[tid - off] : 0;
        __syncthreads();
        ps[tid] += v;
        __syncthreads();
    }
    int run = ps[tid] - s;  // exclusive
    for (int k = 0; k < CH; k++) {
        int i = base + k;
        if (i < N_NODES) {
            d_rowptr[i] = run;
            d_wofs[i] = run;
            run += d_cnt[i];
        }
    }
    if (tid == 1023) d_rowptr[N_NODES] = ps[1023];
}

__global__ void fill_kernel(const int* __restrict__ edge_index) {
    int e = blockIdx.x * blockDim.x + threadIdx.x;
    if (e < N_EDGES) {
        int src = edge_index[e];
        int dst = edge_index[N_EDGES + e];
        int pos = atomicAdd(&d_wofs[dst], 1);
        d_colidx[pos] = src;
        d_eval[pos] = d_dinv[src] * d_dinv[dst];
    }
}

__global__ void embed_kernel(const int* __restrict__ type_ids,
                             const float* __restrict__ other,
                             const float* __restrict__ emb) {
    int i = blockIdx.x;
    int c = threadIdx.x;
    if (c < IN_GNN) {
        float v;
        if (c < EMB_DIM) v = emb[type_ids[i] * EMB_DIM + c];
        else v = other[i * (IN_CH - 1) + (c - EMB_DIM)];
        d_x[i * IN_GNN + c] = v;
    }
}

// ---------------- tiled fp32 GEMM: C = A @ B ----------------------------------
// A [M,K] row-major, B [K,Nn] row-major, C [M,Nn]
#define BM 64
#define BN 64
#define BKD 16
#define TM 4
#define TN 4
__global__ __launch_bounds__(256) void gemm_kernel(
    const float* __restrict__ A, const float* __restrict__ B,
    float* __restrict__ C, int M, int Nn, int K) {
    __shared__ float As[BKD][BM + 1];
    __shared__ float Bs[BKD][BN];
    int tid = threadIdx.x;
    int tx = tid % 16, ty = tid / 16;
    int row0 = blockIdx.y * BM, col0 = blockIdx.x * BN;
    float acc[TM][TN] = {};
    for (int k0 = 0; k0 < K; k0 += BKD) {
        #pragma unroll
        for (int l = tid; l < BM * BKD; l += 256) {
            int m = l / BKD, k = l % BKD;
            float v = 0.0f;
            if (row0 + m < M && k0 + k < K) v = A[(row0 + m) * K + k0 + k];
            As[k][m] = v;
        }
        #pragma unroll
        for (int l = tid; l < BKD * BN; l += 256) {
            int k = l / BN, n = l % BN;
            float v = 0.0f;
            if (k0 + k < K) v = B[(k0 + k) * Nn + col0 + n];  // Nn multiple of 64
            Bs[k][n] = v;
        }
        __syncthreads();
        #pragma unroll
        for (int k = 0; k < BKD; k++) {
            float a[TM], b[TN];
            #pragma unroll
            for (int i = 0; i < TM; i++) a[i] = As[k][ty * TM + i];
            #pragma unroll
            for (int j = 0; j < TN; j++) b[j] = Bs[k][tx * TN + j];
            #pragma unroll
            for (int i = 0; i < TM; i++)
                #pragma unroll
                for (int j = 0; j < TN; j++)
                    acc[i][j] = fmaf(a[i], b[j], acc[i][j]);
        }
        __syncthreads();
    }
    #pragma unroll
    for (int i = 0; i < TM; i++) {
        int m = row0 + ty * TM + i;
        if (m < M) {
            #pragma unroll
            for (int j = 0; j < TN; j++)
                C[m * Nn + col0 + tx * TN + j] = acc[i][j];
        }
    }
}

// ---------------- SpMM (CSR gather) + self loop + bias + ReLU -----------------
__global__ void spmm_relu_kernel(const float* __restrict__ h,
                                 const float* __restrict__ bias,
                                 float* __restrict__ out, int C) {
    int i = blockIdx.x;
    int c = blockIdx.y * blockDim.x + threadIdx.x;
    if (c >= C) return;
    float di = d_dinv[i];
    float acc = di * di * h[i * C + c];
    int e0 = d_rowptr[i], e1 = d_rowptr[i + 1];
    for (int e = e0; e < e1; e++)
        acc += d_eval[e] * h[d_colidx[e] * C + c];
    acc += bias[c];
    out[i * C + c] = acc > 0.0f ? acc : 0.0f;
}

// ---------------- pooling ------------------------------------------------------
__global__ void gcnt_kernel(const int* __restrict__ batch) {
    int i = blockIdx.x * blockDim.x + threadIdx.x;
    if (i < N_NODES) atomicAdd(&d_gcnt[batch[i]], 1.0f);
}

#define POOL_CHUNK 64
__global__ void pool_kernel(const float* __restrict__ h,
                            const int* __restrict__ batch) {
    int c = blockIdx.y * blockDim.x + threadIdx.x;  // channel (C3=1024)
    int i0 = blockIdx.x * POOL_CHUNK;
    int iend = min(i0 + POOL_CHUNK, N_NODES);
    if (i0 >= N_NODES) return;
    float acc = 0.0f;
    int cur = batch[i0];
    for (int i = i0; i < iend; i++) {
        int b = batch[i];
        if (b != cur) {
            atomicAdd(&d_pool[cur * C3 + c], acc);
            acc = 0.0f;
            cur = b;
        }
        acc += h[i * C3 + c];
    }
    atomicAdd(&d_pool[cur * C3 + c], acc);
}

__global__ void mean_kernel() {
    int i = blockIdx.x * blockDim.x + threadIdx.x;
    if (i < NUM_GRAPHS * C3) {
        int g = i / C3;
        d_pool[i] /= fmaxf(d_gcnt[g], 1.0f);
    }
}

// ---------------- small MLP layer ---------------------------------------------
// in [G,K], W [K,Mo] row-major, out [G,Mo]; one block row (grid.y=G)
__global__ void mlp_kernel(const float* __restrict__ in,
                           const float* __restrict__ W,
                           const float* __restrict__ bias,
                           float* __restrict__ out,
                           int K, int Mo, int do_relu) {
    __shared__ float sin[1024];
    int row = blockIdx.y;
    for (int k = threadIdx.x; k < K; k += blockDim.x) sin[k] = in[row * K + k];
    __syncthreads();
    int col = blockIdx.x * blockDim.x + threadIdx.x;
    if (col < Mo) {
        float acc = bias[col];
        for (int k = 0; k < K; k++)
            acc = fmaf(sin[k], W[k * Mo + col], acc);
        if (do_relu) acc = acc > 0.0f ? acc : 0.0f;
        out[row * Mo + col] = acc;
    }
}

// ---------------- launch -------------------------------------------------------
extern "C" void kernel_launch(void* const* d_in, const int* in_sizes, int n_in,
                              void* d_out, int out_size) {
    const int*   type_ids = (const int*)  d_in[0];
    const float* other    = (const float*)d_in[1];
    const int*   eidx     = (const int*)  d_in[2];
    const int*   batch    = (const int*)  d_in[3];
    const float* emb      = (const float*)d_in[4];
    const float* W1 = (const float*)d_in[5];  const float* b1 = (const float*)d_in[6];
    const float* W2 = (const float*)d_in[7];  const float* b2 = (const float*)d_in[8];
    const float* W3 = (const float*)d_in[9];  const float* b3 = (const float*)d_in[10];
    const float* h1w = (const float*)d_in[11]; const float* h1b = (const float*)d_in[12];
    const float* h2w = (const float*)d_in[13]; const float* h2b = (const float*)d_in[14];
    const float* h3w = (const float*)d_in[15]; const float* h3b = (const float*)d_in[16];
    const float* ow  = (const float*)d_in[17]; const float* ob  = (const float*)d_in[18];
    float* out = (float*)d_out;

    float* x_p;    cudaGetSymbolAddress((void**)&x_p,   d_x);
    float* h_p;    cudaGetSymbolAddress((void**)&h_p,   d_h);
    float* agg_p;  cudaGetSymbolAddress((void**)&agg_p, d_agg);
    float* pool_p; cudaGetSymbolAddress((void**)&pool_p, d_pool);
    float* m1_p;   cudaGetSymbolAddress((void**)&m1_p,  d_m1);
    float* m2_p;   cudaGetSymbolAddress((void**)&m2_p,  d_m2);
    float* m3_p;   cudaGetSymbolAddress((void**)&m3_p,  d_m3);

    // --- graph structure ---
    init_kernel<<<128, 256>>>();
    count_kernel<<<(N_EDGES + 255) / 256, 256>>>(eidx);
    dinv_kernel<<<(N_NODES + 255) / 256, 256>>>();
    scan_kernel<<<1, 1024>>>();
    fill_kernel<<<(N_EDGES + 255) / 256, 256>>>(eidx);
    gcnt_kernel<<<(N_NODES + 255) / 256, 256>>>(batch);

    // --- node features ---
    embed_kernel<<<N_NODES, 192>>>(type_ids, other, emb);

    // --- GCN layer 1: [N,191] @ [191,2048] ---
    {
        dim3 grid(C1 / BN, (N_NODES + BM - 1) / BM);
        gemm_kernel<<<grid, 256>>>(x_p, W1, h_p, N_NODES, C1, IN_GNN);
        dim3 sgrid(N_NODES, C1 / 256);
        spmm_relu_kernel<<<sgrid, 256>>>(h_p, b1, agg_p, C1);
    }
    // --- GCN layer 2: [N,2048] @ [2048,1024] ---
    {
        dim3 grid(C2 / BN, (N_NODES + BM - 1) / BM);
        gemm_kernel<<<grid, 256>>>(agg_p, W2, h_p, N_NODES, C2, C1);
        dim3 sgrid(N_NODES, C2 / 256);
        spmm_relu_kernel<<<sgrid, 256>>>(h_p, b2, agg_p, C2);
    }
    // --- GCN layer 3: [N,1024] @ [1024,1024] ---
    {
        dim3 grid(C3 / BN, (N_NODES + BM - 1) / BM);
        gemm_kernel<<<grid, 256>>>(agg_p, W3, h_p, N_NODES, C3, C2);
        dim3 sgrid(N_NODES, C3 / 256);
        spmm_relu_kernel<<<sgrid, 256>>>(h_p, b3, agg_p, C3);
    }

    // --- global mean pool ---
    {
        dim3 grid((N_NODES + POOL_CHUNK - 1) / POOL_CHUNK, C3 / 256);
        pool_kernel<<<grid, 256>>>(agg_p, batch);
        mean_kernel<<<(NUM_GRAPHS * C3 + 255) / 256, 256>>>();
    }

    // --- MLP head ---
    {
        dim3 g1(1024 / 256, NUM_GRAPHS);
        mlp_kernel<<<g1, 256>>>(pool_p, h1w, h1b, m1_p, 1024, 1024, 1);
        mlp_kernel<<<g1, 256>>>(m1_p, h2w, h2b, m2_p, 1024, 1024, 1);
        dim3 g3(H3 / 256, NUM_GRAPHS);
        mlp_kernel<<<g3, 256>>>(m2_p, h3w, h3b, m3_p, 1024, H3, 1);
        dim3 g4(1, NUM_GRAPHS);
        mlp_kernel<<<g4, 256>>>(m3_p, ow, ob, out, H3, NUM_CLASSES, 0);
    }
}

// round 3
// speedup vs baseline: 1.9838x; 1.9838x over previous
#include <cuda_runtime.h>
#include <cuda_bf16.h>
#include <math.h>
#include <stdint.h>

#define N_NODES 10000
#define N_EDGES 80000
#define EMB_DIM 128
#define IN_CH 64
#define IN_GNN 191
#define K1PAD 192
#define C1 2048
#define C2 1024
#define C3 1024
#define NUM_GRAPHS 16
#define H3 512
#define NUM_CLASSES 2

// ---------------- scratch (device globals) ------------------------------------
__device__ float d_x[N_NODES * IN_GNN];
__device__ float d_h[N_NODES * C1];
__device__ float d_agg[N_NODES * C1];
__device__ __nv_bfloat16 d_ah[N_NODES * C1];     // activation hi
__device__ __nv_bfloat16 d_al[N_NODES * C1];     // activation lo
__device__ __nv_bfloat16 d_wth[C1 * C1];         // W^T hi [Nn,Kpad]
__device__ __nv_bfloat16 d_wtl[C1 * C1];         // W^T lo
__device__ float d_dinv[N_NODES];
__device__ int   d_cnt[N_NODES];
__device__ int   d_rowptr[N_NODES + 1];
__device__ int   d_wofs[N_NODES];
__device__ int   d_colidx[N_EDGES];
__device__ float d_eval[N_EDGES];
__device__ float d_pool[NUM_GRAPHS * C3];
__device__ float d_gcnt[NUM_GRAPHS];
__device__ float d_m1[NUM_GRAPHS * 1024];
__device__ float d_m2[NUM_GRAPHS * 1024];
__device__ float d_m3[NUM_GRAPHS * H3];

// ---------------- helpers -------------------------------------------------------
__device__ __forceinline__ uint32_t smem_u32(const void* p) {
    uint32_t a;
    asm("{ .reg .u64 t; cvta.to.shared.u64 t, %1; cvt.u32.u64 %0, t; }"
        : "=r"(a) : "l"(p));
    return a;
}
__device__ __forceinline__ void cp16(uint32_t dst, const void* src, bool pred) {
    int sz = pred ? 16 : 0;
    asm volatile("cp.async.cg.shared.global [%0], [%1], 16, %2;"
                 :: "r"(dst), "l"(src), "r"(sz) : "memory");
}
#define CP_COMMIT() asm volatile("cp.async.commit_group;" ::: "memory")
#define CP_WAIT1()  asm volatile("cp.async.wait_group 1;" ::: "memory")

__device__ __forceinline__ void ldsm4(uint32_t (&r)[4], uint32_t a) {
    asm volatile("ldmatrix.sync.aligned.m8n8.x4.shared.b16 {%0,%1,%2,%3}, [%4];"
        : "=r"(r[0]), "=r"(r[1]), "=r"(r[2]), "=r"(r[3]) : "r"(a));
}
__device__ __forceinline__ void mma16816(float (&d)[4], const uint32_t (&a)[4],
                                         const uint32_t* b) {
    asm volatile("mma.sync.aligned.m16n8k16.row.col.f32.bf16.bf16.f32 "
        "{%0,%1,%2,%3}, {%4,%5,%6,%7}, {%8,%9}, {%0,%1,%2,%3};"
        : "+f"(d[0]), "+f"(d[1]), "+f"(d[2]), "+f"(d[3])
        : "r"(a[0]), "r"(a[1]), "r"(a[2]), "r"(a[3]), "r"(b[0]), "r"(b[1]));
}

// ---------------- setup kernels -------------------------------------------------
__global__ void init_kernel() {
    int i = blockIdx.x * blockDim.x + threadIdx.x;
    int total = N_NODES + NUM_GRAPHS * C3 + NUM_GRAPHS;
    for (; i < total; i += gridDim.x * blockDim.x) {
        if (i < N_NODES) d_cnt[i] = 0;
        else if (i < N_NODES + NUM_GRAPHS * C3) d_pool[i - N_NODES] = 0.0f;
        else d_gcnt[i - N_NODES - NUM_GRAPHS * C3] = 0.0f;
    }
}
__global__ void count_kernel(const int* __restrict__ ei) {
    int e = blockIdx.x * blockDim.x + threadIdx.x;
    if (e < N_EDGES) atomicAdd(&d_cnt[ei[N_EDGES + e]], 1);
}
__global__ void dinv_kernel() {
    int i = blockIdx.x * blockDim.x + threadIdx.x;
    if (i < N_NODES) d_dinv[i] = rsqrtf((float)(d_cnt[i] + 1));
}
__global__ void scan_kernel() {
    __shared__ int ps[1024];
    const int CH = (N_NODES + 1023) / 1024;
    int tid = threadIdx.x, base = tid * CH, s = 0;
    for (int k = 0; k < CH; k++) { int i = base + k; if (i < N_NODES) s += d_cnt[i]; }
    ps[tid] = s; __syncthreads();
    for (int off = 1; off < 1024; off <<= 1) {
        int v = (tid >= off) ? ps[tid - off] : 0;
        __syncthreads(); ps[tid] += v; __syncthreads();
    }
    int run = ps[tid] - s;
    for (int k = 0; k < CH; k++) {
        int i = base + k;
        if (i < N_NODES) { d_rowptr[i] = run; d_wofs[i] = run; run += d_cnt[i]; }
    }
    if (tid == 1023) d_rowptr[N_NODES] = ps[1023];
}
__global__ void fill_kernel(const int* __restrict__ ei) {
    int e = blockIdx.x * blockDim.x + threadIdx.x;
    if (e < N_EDGES) {
        int src = ei[e], dst = ei[N_EDGES + e];
        int pos = atomicAdd(&d_wofs[dst], 1);
        d_colidx[pos] = src;
        d_eval[pos] = d_dinv[src] * d_dinv[dst];
    }
}
__global__ void embed_kernel(const int* __restrict__ tids,
                             const float* __restrict__ other,
                             const float* __restrict__ emb) {
    int i = blockIdx.x, c = threadIdx.x;
    if (c < IN_GNN) {
        float v = (c < EMB_DIM) ? emb[tids[i] * EMB_DIM + c]
                                : other[i * (IN_CH - 1) + (c - EMB_DIM)];
        d_x[i * IN_GNN + c] = v;
    }
}
__global__ void gcnt_kernel(const int* __restrict__ batch) {
    int i = blockIdx.x * blockDim.x + threadIdx.x;
    if (i < N_NODES) atomicAdd(&d_gcnt[batch[i]], 1.0f);
}

// ---------------- split / transpose ---------------------------------------------
__global__ void split_x_kernel(const float* __restrict__ src, int Kin, int Kpad) {
    long idx = (long)blockIdx.x * blockDim.x + threadIdx.x;
    long total = (long)N_NODES * Kpad;
    if (idx >= total) return;
    int i = (int)(idx / Kpad), k = (int)(idx % Kpad);
    float x = (k < Kin) ? src[(long)i * Kin + k] : 0.0f;
    __nv_bfloat16 hi = __float2bfloat16(x);
    float r = x - __bfloat162float(hi);
    d_ah[idx] = hi;
    d_al[idx] = __float2bfloat16(r);
}
__global__ void tsplit_w_kernel(const float* __restrict__ W, int Kin, int Kpad, int Nn) {
    __shared__ float t[32][33];
    int k0 = blockIdx.x * 32, n0 = blockIdx.y * 32;
    int tx = threadIdx.x, ty = threadIdx.y;
    int k = k0 + ty, n = n0 + tx;
    t[ty][tx] = (k < Kin) ? W[(long)k * Nn + n] : 0.0f;
    __syncthreads();
    int nw = n0 + ty, kw = k0 + tx;
    float x = t[tx][ty];
    __nv_bfloat16 hi = __float2bfloat16(x);
    float r = x - __bfloat162float(hi);
    long o = (long)nw * Kpad + kw;
    d_wth[o] = hi;
    d_wtl[o] = __float2bfloat16(r);
}

// ---------------- mma.sync bf16-split GEMM --------------------------------------
// C[M,Nn] = A[M,Kp] @ Wt[Nn,Kp]^T, fp32 accum, 3-term split emulation.
#define BM 128
#define BN 128
#define BK 32
#define TILE_BYTES (128 * 32 * 2)      // 8 KB per tile
#define STAGE_BYTES (4 * TILE_BYTES)   // 32 KB (Ah, Al, Bh, Bl)

__global__ __launch_bounds__(256) void mma_gemm_kernel(
    const __nv_bfloat16* __restrict__ Ah, const __nv_bfloat16* __restrict__ Al,
    const __nv_bfloat16* __restrict__ Bh, const __nv_bfloat16* __restrict__ Bl,
    float* __restrict__ C, int M, int Nn, int Kp) {
    extern __shared__ char smem[];
    uint32_t sbase = smem_u32(smem);
    int tid = threadIdx.x;
    int row0 = blockIdx.y * BM, col0 = blockIdx.x * BN;
    int nkt = Kp / BK;

    int w = tid >> 5, lane = tid & 31;
    int wm = (w & 3) * 32;   // 4 warps along M
    int wn = (w >> 2) * 64;  // 2 warps along N
    int q = lane >> 3, rr = lane & 7;

    float acc[2][8][4] = {};

    // stage loader: 4 tiles x 128 rows x 4 x 16B chunks = 2048 units
    auto issue_stage = [&](int kt, int stage) {
        int k0 = kt * BK;
        #pragma unroll
        for (int i = 0; i < 8; i++) {
            int idx = tid + i * 256;
            int t = idx >> 9;
            int r = (idx >> 2) & 127;
            int c = idx & 3;
            int grow = ((t < 2) ? row0 : col0) + r;
            bool ok = (t >= 2) || (grow < M);
            const __nv_bfloat16* s = (t == 0) ? Ah : (t == 1) ? Al : (t == 2) ? Bh : Bl;
            const char* gp = (const char*)(s + (size_t)(ok ? grow : 0) * Kp + k0) + c * 16;
            uint32_t so = sbase + stage * STAGE_BYTES + t * TILE_BYTES
                        + r * 64 + ((c ^ ((r >> 1) & 3)) << 4);
            cp16(so, gp, ok);
        }
        CP_COMMIT();
    };

    issue_stage(0, 0);
    if (nkt > 1) issue_stage(1, 1); else CP_COMMIT();

    for (int kt = 0; kt < nkt; kt++) {
        CP_WAIT1();
        __syncthreads();
        int st = kt & 1;
        uint32_t abase = sbase + st * STAGE_BYTES;
        uint32_t bbase = abase + 2 * TILE_BYTES;
        #pragma unroll
        for (int ks = 0; ks < 2; ks++) {
            uint32_t ah[2][4], al[2][4];
            #pragma unroll
            for (int mf = 0; mf < 2; mf++) {
                int row = wm + mf * 16 + (q & 1) * 8 + rr;
                int c = 2 * ks + (q >> 1);
                uint32_t off = row * 64 + ((c ^ ((row >> 1) & 3)) << 4);
                ldsm4(ah[mf], abase + off);
                ldsm4(al[mf], abase + TILE_BYTES + off);
            }
            uint32_t bfr[8][2];
            // --- B hi: acc += Ah*Bh + Al*Bh ---
            #pragma unroll
            for (int nf2 = 0; nf2 < 4; nf2++) {
                int n = wn + nf2 * 16 + (q >> 1) * 8 + rr;
                int c = 2 * ks + (q & 1);
                uint32_t off = n * 64 + ((c ^ ((n >> 1) & 3)) << 4);
                uint32_t t0[4];
                ldsm4(t0, bbase + off);
                bfr[2*nf2][0] = t0[0]; bfr[2*nf2][1] = t0[1];
                bfr[2*nf2+1][0] = t0[2]; bfr[2*nf2+1][1] = t0[3];
            }
            #pragma unroll
            for (int mf = 0; mf < 2; mf++)
                #pragma unroll
                for (int nf = 0; nf < 8; nf++) {
                    mma16816(acc[mf][nf], ah[mf], bfr[nf]);
                    mma16816(acc[mf][nf], al[mf], bfr[nf]);
                }
            // --- B lo: acc += Ah*Bl ---
            #pragma unroll
            for (int nf2 = 0; nf2 < 4; nf2++) {
                int n = wn + nf2 * 16 + (q >> 1) * 8 + rr;
                int c = 2 * ks + (q & 1);
                uint32_t off = n * 64 + ((c ^ ((n >> 1) & 3)) << 4);
                uint32_t t1[4];
                ldsm4(t1, bbase + TILE_BYTES + off);
                bfr[2*nf2][0] = t1[0]; bfr[2*nf2][1] = t1[1];
                bfr[2*nf2+1][0] = t1[2]; bfr[2*nf2+1][1] = t1[3];
            }
            #pragma unroll
            for (int mf = 0; mf < 2; mf++)
                #pragma unroll
                for (int nf = 0; nf < 8; nf++)
                    mma16816(acc[mf][nf], ah[mf], bfr[nf]);
        }
        __syncthreads();
        if (kt + 2 < nkt) issue_stage(kt + 2, st);
        else CP_COMMIT();
    }

    // epilogue
    #pragma unroll
    for (int mf = 0; mf < 2; mf++) {
        int r0 = row0 + wm + mf * 16 + (lane >> 2);
        #pragma unroll
        for (int nf = 0; nf < 8; nf++) {
            int cc = col0 + wn + nf * 8 + (lane & 3) * 2;
            if (r0 < M)
                *(float2*)(C + (size_t)r0 * Nn + cc) =
                    make_float2(acc[mf][nf][0], acc[mf][nf][1]);
            if (r0 + 8 < M)
                *(float2*)(C + (size_t)(r0 + 8) * Nn + cc) =
                    make_float2(acc[mf][nf][2], acc[mf][nf][3]);
        }
    }
}

// ---------------- SpMM (CSR gather) + self loop + bias + ReLU -------------------
__global__ void spmm_relu_kernel(const float* __restrict__ h,
                                 const float* __restrict__ bias,
                                 float* __restrict__ out, int C) {
    int i = blockIdx.x;
    int c = blockIdx.y * blockDim.x + threadIdx.x;
    if (c >= C) return;
    float di = d_dinv[i];
    float acc = di * di * h[i * C + c];
    int e0 = d_rowptr[i], e1 = d_rowptr[i + 1];
    for (int e = e0; e < e1; e++)
        acc += d_eval[e] * h[d_colidx[e] * C + c];
    acc += bias[c];
    out[i * C + c] = acc > 0.0f ? acc : 0.0f;
}

// ---------------- pooling -------------------------------------------------------
#define POOL_CHUNK 64
__global__ void pool_kernel(const float* __restrict__ h,
                            const int* __restrict__ batch) {
    int c = blockIdx.y * blockDim.x + threadIdx.x;
    int i0 = blockIdx.x * POOL_CHUNK;
    int iend = min(i0 + POOL_CHUNK, N_NODES);
    if (i0 >= N_NODES) return;
    float acc = 0.0f;
    int cur = batch[i0];
    for (int i = i0; i < iend; i++) {
        int b = batch[i];
        if (b != cur) { atomicAdd(&d_pool[cur * C3 + c], acc); acc = 0.0f; cur = b; }
        acc += h[i * C3 + c];
    }
    atomicAdd(&d_pool[cur * C3 + c], acc);
}
__global__ void mean_kernel() {
    int i = blockIdx.x * blockDim.x + threadIdx.x;
    if (i < NUM_GRAPHS * C3) d_pool[i] /= fmaxf(d_gcnt[i / C3], 1.0f);
}

// ---------------- small MLP -----------------------------------------------------
__global__ void mlp_kernel(const float* __restrict__ in,
                           const float* __restrict__ W,
                           const float* __restrict__ bias,
                           float* __restrict__ out,
                           int K, int Mo, int do_relu) {
    __shared__ float sin[1024];
    int row = blockIdx.y;
    for (int k = threadIdx.x; k < K; k += blockDim.x) sin[k] = in[row * K + k];
    __syncthreads();
    int col = blockIdx.x * blockDim.x + threadIdx.x;
    if (col < Mo) {
        float acc = bias[col];
        for (int k = 0; k < K; k++) acc = fmaf(sin[k], W[k * Mo + col], acc);
        if (do_relu) acc = acc > 0.0f ? acc : 0.0f;
        out[row * Mo + col] = acc;
    }
}

// ---------------- launch --------------------------------------------------------
extern "C" void kernel_launch(void* const* d_in, const int* in_sizes, int n_in,
                              void* d_out, int out_size) {
    const int*   type_ids = (const int*)  d_in[0];
    const float* other    = (const float*)d_in[1];
    const int*   eidx     = (const int*)  d_in[2];
    const int*   batch    = (const int*)  d_in[3];
    const float* emb      = (const float*)d_in[4];
    const float* W1 = (const float*)d_in[5];  const float* b1 = (const float*)d_in[6];
    const float* W2 = (const float*)d_in[7];  const float* b2 = (const float*)d_in[8];
    const float* W3 = (const float*)d_in[9];  const float* b3 = (const float*)d_in[10];
    const float* h1w = (const float*)d_in[11]; const float* h1b = (const float*)d_in[12];
    const float* h2w = (const float*)d_in[13]; const float* h2b = (const float*)d_in[14];
    const float* h3w = (const float*)d_in[15]; const float* h3b = (const float*)d_in[16];
    const float* ow  = (const float*)d_in[17]; const float* ob  = (const float*)d_in[18];
    float* out = (float*)d_out;

    float* x_p;    cudaGetSymbolAddress((void**)&x_p,   d_x);
    float* h_p;    cudaGetSymbolAddress((void**)&h_p,   d_h);
    float* agg_p;  cudaGetSymbolAddress((void**)&agg_p, d_agg);
    float* pool_p; cudaGetSymbolAddress((void**)&pool_p, d_pool);
    float* m1_p;   cudaGetSymbolAddress((void**)&m1_p,  d_m1);
    float* m2_p;   cudaGetSymbolAddress((void**)&m2_p,  d_m2);
    float* m3_p;   cudaGetSymbolAddress((void**)&m3_p,  d_m3);
    __nv_bfloat16* ah_p; cudaGetSymbolAddress((void**)&ah_p, d_ah);
    __nv_bfloat16* al_p; cudaGetSymbolAddress((void**)&al_p, d_al);
    __nv_bfloat16* wh_p; cudaGetSymbolAddress((void**)&wh_p, d_wth);
    __nv_bfloat16* wl_p; cudaGetSymbolAddress((void**)&wl_p, d_wtl);

    static int smem_set = 0;
    if (!smem_set) {
        cudaFuncSetAttribute(mma_gemm_kernel,
                             cudaFuncAttributeMaxDynamicSharedMemorySize,
                             2 * STAGE_BYTES);
        smem_set = 1;
    }

    // graph structure
    init_kernel<<<128, 256>>>();
    count_kernel<<<(N_EDGES + 255) / 256, 256>>>(eidx);
    dinv_kernel<<<(N_NODES + 255) / 256, 256>>>();
    scan_kernel<<<1, 1024>>>();
    fill_kernel<<<(N_EDGES + 255) / 256, 256>>>(eidx);
    gcnt_kernel<<<(N_NODES + 255) / 256, 256>>>(batch);
    embed_kernel<<<N_NODES, 192>>>(type_ids, other, emb);

    const int MT = (N_NODES + BM - 1) / BM;  // 79

    // --- layer 1: [N,192pad] @ W1t -> h [N,2048] ---
    {
        long tot = (long)N_NODES * K1PAD;
        split_x_kernel<<<(int)((tot + 255) / 256), 256>>>(x_p, IN_GNN, K1PAD);
        dim3 tg(K1PAD / 32, C1 / 32);
        tsplit_w_kernel<<<tg, dim3(32, 32)>>>(W1, IN_GNN, K1PAD, C1);
        dim3 grid(C1 / BN, MT);
        mma_gemm_kernel<<<grid, 256, 2 * STAGE_BYTES>>>(ah_p, al_p, wh_p, wl_p,
                                                        h_p, N_NODES, C1, K1PAD);
        dim3 sg(N_NODES, C1 / 256);
        spmm_relu_kernel<<<sg, 256>>>(h_p, b1, agg_p, C1);
    }
    // --- layer 2: [N,2048] @ W2t -> h [N,1024] ---
    {
        long tot = (long)N_NODES * C1;
        split_x_kernel<<<(int)((tot + 255) / 256), 256>>>(agg_p, C1, C1);
        dim3 tg(C1 / 32, C2 / 32);
        tsplit_w_kernel<<<tg, dim3(32, 32)>>>(W2, C1, C1, C2);
        dim3 grid(C2 / BN, MT);
        mma_gemm_kernel<<<grid, 256, 2 * STAGE_BYTES>>>(ah_p, al_p, wh_p, wl_p,
                                                        h_p, N_NODES, C2, C1);
        dim3 sg(N_NODES, C2 / 256);
        spmm_relu_kernel<<<sg, 256>>>(h_p, b2, agg_p, C2);
    }
    // --- layer 3: [N,1024] @ W3t -> h [N,1024] ---
    {
        long tot = (long)N_NODES * C2;
        split_x_kernel<<<(int)((tot + 255) / 256), 256>>>(agg_p, C2, C2);
        dim3 tg(C2 / 32, C3 / 32);
        tsplit_w_kernel<<<tg, dim3(32, 32)>>>(W3, C2, C2, C3);
        dim3 grid(C3 / BN, MT);
        mma_gemm_kernel<<<grid, 256, 2 * STAGE_BYTES>>>(ah_p, al_p, wh_p, wl_p,
                                                        h_p, N_NODES, C3, C2);
        dim3 sg(N_NODES, C3 / 256);
        spmm_relu_kernel<<<sg, 256>>>(h_p, b3, agg_p, C3);
    }

    // pool + head
    {
        dim3 grid((N_NODES + POOL_CHUNK - 1) / POOL_CHUNK, C3 / 256);
        pool_kernel<<<grid, 256>>>(agg_p, batch);
        mean_kernel<<<(NUM_GRAPHS * C3 + 255) / 256, 256>>>();
        dim3 g1(1024 / 256, NUM_GRAPHS);
        mlp_kernel<<<g1, 256>>>(pool_p, h1w, h1b, m1_p, 1024, 1024, 1);
        mlp_kernel<<<g1, 256>>>(m1_p, h2w, h2b, m2_p, 1024, 1024, 1);
        dim3 g3(H3 / 256, NUM_GRAPHS);
        mlp_kernel<<<g3, 256>>>(m2_p, h3w, h3b, m3_p, 1024, H3, 1);
        dim3 g4(1, NUM_GRAPHS);
        mlp_kernel<<<g4, 256>>>(m3_p, ow, ob, out, H3, NUM_CLASSES, 0);
    }
}

// round 4
// speedup vs baseline: 3.3912x; 1.7094x over previous
#include <cuda_runtime.h>
#include <cuda_fp16.h>
#include <math.h>
#include <stdint.h>

#define N_NODES 10000
#define N_EDGES 80000
#define EMB_DIM 128
#define IN_CH 64
#define IN_GNN 191
#define K1PAD 192
#define C1 2048
#define C2 1024
#define C3 1024
#define NUM_GRAPHS 16
#define H3 512
#define NUM_CLASSES 2

// ---------------- scratch (device globals) ------------------------------------
__device__ float  d_h[N_NODES * C1];             // GEMM output (fp32)
__device__ float  d_agg[N_NODES * C3];           // layer-3 aggregated fp32 (for pool)
__device__ __half d_a16[N_NODES * C1];           // fp16 activations (GEMM A input)
__device__ __half d_wt16[C1 * C1];               // W^T fp16 [Nn, Kpad]
__device__ float  d_dinv[N_NODES];
__device__ int    d_cnt[N_NODES];
__device__ int    d_rowptr[N_NODES + 1];
__device__ int    d_wofs[N_NODES];
__device__ int    d_colidx[N_EDGES];
__device__ float  d_eval[N_EDGES];
__device__ float  d_pool[NUM_GRAPHS * C3];
__device__ float  d_gcnt[NUM_GRAPHS];
__device__ float  d_m1[NUM_GRAPHS * 1024];
__device__ float  d_m2[NUM_GRAPHS * 1024];
__device__ float  d_m3[NUM_GRAPHS * H3];

// ---------------- helpers -------------------------------------------------------
__device__ __forceinline__ uint32_t smem_u32(const void* p) {
    uint32_t a;
    asm("{ .reg .u64 t; cvta.to.shared.u64 t, %1; cvt.u32.u64 %0, t; }"
        : "=r"(a) : "l"(p));
    return a;
}
__device__ __forceinline__ void cp16(uint32_t dst, const void* src, bool pred) {
    int sz = pred ? 16 : 0;
    asm volatile("cp.async.cg.shared.global [%0], [%1], 16, %2;"
                 :: "r"(dst), "l"(src), "r"(sz) : "memory");
}
#define CP_COMMIT() asm volatile("cp.async.commit_group;" ::: "memory")
#define CP_WAIT3()  asm volatile("cp.async.wait_group 3;" ::: "memory")

__device__ __forceinline__ void ldsm4(uint32_t (&r)[4], uint32_t a) {
    asm volatile("ldmatrix.sync.aligned.m8n8.x4.shared.b16 {%0,%1,%2,%3}, [%4];"
        : "=r"(r[0]), "=r"(r[1]), "=r"(r[2]), "=r"(r[3]) : "r"(a));
}
__device__ __forceinline__ void mma16816(float (&d)[4], const uint32_t (&a)[4],
                                         const uint32_t* b) {
    asm volatile("mma.sync.aligned.m16n8k16.row.col.f32.f16.f16.f32 "
        "{%0,%1,%2,%3}, {%4,%5,%6,%7}, {%8,%9}, {%0,%1,%2,%3};"
        : "+f"(d[0]), "+f"(d[1]), "+f"(d[2]), "+f"(d[3])
        : "r"(a[0]), "r"(a[1]), "r"(a[2]), "r"(a[3]), "r"(b[0]), "r"(b[1]));
}

// ---------------- setup kernels -------------------------------------------------
__global__ void init_kernel() {
    int i = blockIdx.x * blockDim.x + threadIdx.x;
    int total = N_NODES + NUM_GRAPHS * C3 + NUM_GRAPHS;
    for (; i < total; i += gridDim.x * blockDim.x) {
        if (i < N_NODES) d_cnt[i] = 0;
        else if (i < N_NODES + NUM_GRAPHS * C3) d_pool[i - N_NODES] = 0.0f;
        else d_gcnt[i - N_NODES - NUM_GRAPHS * C3] = 0.0f;
    }
}
__global__ void count_kernel(const int* __restrict__ ei) {
    int e = blockIdx.x * blockDim.x + threadIdx.x;
    if (e < N_EDGES) atomicAdd(&d_cnt[ei[N_EDGES + e]], 1);
}
__global__ void dinv_kernel() {
    int i = blockIdx.x * blockDim.x + threadIdx.x;
    if (i < N_NODES) d_dinv[i] = rsqrtf((float)(d_cnt[i] + 1));
}
__global__ void scan_kernel() {
    __shared__ int ps[1024];
    const int CH = (N_NODES + 1023) / 1024;
    int tid = threadIdx.x, base = tid * CH, s = 0;
    for (int k = 0; k < CH; k++) { int i = base + k; if (i < N_NODES) s += d_cnt[i]; }
    ps[tid] = s; __syncthreads();
    for (int off = 1; off < 1024; off <<= 1) {
        int v = (tid >= off) ? ps[tid - off] : 0;
        __syncthreads(); ps[tid] += v; __syncthreads();
    }
    int run = ps[tid] - s;
    for (int k = 0; k < CH; k++) {
        int i = base + k;
        if (i < N_NODES) { d_rowptr[i] = run; d_wofs[i] = run; run += d_cnt[i]; }
    }
    if (tid == 1023) d_rowptr[N_NODES] = ps[1023];
}
__global__ void fill_kernel(const int* __restrict__ ei) {
    int e = blockIdx.x * blockDim.x + threadIdx.x;
    if (e < N_EDGES) {
        int src = ei[e], dst = ei[N_EDGES + e];
        int pos = atomicAdd(&d_wofs[dst], 1);
        d_colidx[pos] = src;
        d_eval[pos] = d_dinv[src] * d_dinv[dst];
    }
}
// embed + concat straight to fp16 A (padded to K1PAD)
__global__ void embed_kernel(const int* __restrict__ tids,
                             const float* __restrict__ other,
                             const float* __restrict__ emb) {
    int i = blockIdx.x, c = threadIdx.x;  // c in [0, K1PAD)
    float v = 0.0f;
    if (c < EMB_DIM) v = emb[tids[i] * EMB_DIM + c];
    else if (c < IN_GNN) v = other[i * (IN_CH - 1) + (c - EMB_DIM)];
    d_a16[i * K1PAD + c] = __float2half(v);
}
__global__ void gcnt_kernel(const int* __restrict__ batch) {
    int i = blockIdx.x * blockDim.x + threadIdx.x;
    if (i < N_NODES) atomicAdd(&d_gcnt[batch[i]], 1.0f);
}

// W [Kin, Nn] fp32 -> Wt fp16 [Nn, Kpad]
__global__ void tconv_w_kernel(const float* __restrict__ W, int Kin, int Kpad, int Nn) {
    __shared__ float t[32][33];
    int k0 = blockIdx.x * 32, n0 = blockIdx.y * 32;
    int tx = threadIdx.x, ty = threadIdx.y;
    int k = k0 + ty, n = n0 + tx;
    t[ty][tx] = (k < Kin) ? W[(long)k * Nn + n] : 0.0f;
    __syncthreads();
    int nw = n0 + ty, kw = k0 + tx;
    d_wt16[(long)nw * Kpad + kw] = __float2half(t[tx][ty]);
}

// ---------------- mma.sync fp16 GEMM --------------------------------------------
// C[M,Nn] = A[M,Kp] @ Wt[Nn,Kp]^T, fp32 accum.
#define BM 128
#define BN 128
#define BK 32
#define TILE_BYTES (128 * 32 * 2)      // 8 KB per tile
#define STAGE_BYTES (2 * TILE_BYTES)   // 16 KB (A, B)
#define NSTAGE 4

__global__ __launch_bounds__(256) void mma_gemm_kernel(
    const __half* __restrict__ A, const __half* __restrict__ B,
    float* __restrict__ C, int M, int Nn, int Kp) {
    extern __shared__ char smem[];
    uint32_t sbase = smem_u32(smem);
    int tid = threadIdx.x;
    int row0 = blockIdx.y * BM, col0 = blockIdx.x * BN;
    int nkt = Kp / BK;

    int w = tid >> 5, lane = tid & 31;
    int wm = (w & 3) * 32;   // 4 warps along M
    int wn = (w >> 2) * 64;  // 2 warps along N
    int q = lane >> 3, rr = lane & 7;

    float acc[2][8][4] = {};

    // stage loader: 2 tiles x 128 rows x 4 x 16B chunks = 1024 units (4/thread)
    auto issue_stage = [&](int kt, int slot) {
        int k0 = kt * BK;
        #pragma unroll
        for (int i = 0; i < 4; i++) {
            int idx = tid + i * 256;
            int t = idx >> 9;
            int r = (idx >> 2) & 127;
            int c = idx & 3;
            int grow = ((t == 0) ? row0 : col0) + r;
            bool ok = (t == 1) || (grow < M);
            const __half* s = (t == 0) ? A : B;
            const char* gp = (const char*)(s + (size_t)(ok ? grow : 0) * Kp + k0) + c * 16;
            uint32_t so = sbase + slot * STAGE_BYTES + t * TILE_BYTES
                        + r * 64 + ((c ^ ((r >> 1) & 3)) << 4);
            cp16(so, gp, ok);
        }
        CP_COMMIT();
    };

    #pragma unroll
    for (int s = 0; s < NSTAGE; s++) {
        if (s < nkt) issue_stage(s, s); else CP_COMMIT();
    }

    for (int kt = 0; kt < nkt; kt++) {
        CP_WAIT3();
        __syncthreads();
        int st = kt & 3;
        uint32_t abase = sbase + st * STAGE_BYTES;
        uint32_t bbase = abase + TILE_BYTES;
        #pragma unroll
        for (int ks = 0; ks < 2; ks++) {
            uint32_t ah[2][4];
            #pragma unroll
            for (int mf = 0; mf < 2; mf++) {
                int row = wm + mf * 16 + (q & 1) * 8 + rr;
                int c = 2 * ks + (q >> 1);
                uint32_t off = row * 64 + ((c ^ ((row >> 1) & 3)) << 4);
                ldsm4(ah[mf], abase + off);
            }
            uint32_t bfr[8][2];
            #pragma unroll
            for (int nf2 = 0; nf2 < 4; nf2++) {
                int n = wn + nf2 * 16 + (q >> 1) * 8 + rr;
                int c = 2 * ks + (q & 1);
                uint32_t off = n * 64 + ((c ^ ((n >> 1) & 3)) << 4);
                uint32_t t0[4];
                ldsm4(t0, bbase + off);
                bfr[2*nf2][0] = t0[0]; bfr[2*nf2][1] = t0[1];
                bfr[2*nf2+1][0] = t0[2]; bfr[2*nf2+1][1] = t0[3];
            }
            #pragma unroll
            for (int mf = 0; mf < 2; mf++)
                #pragma unroll
                for (int nf = 0; nf < 8; nf++)
                    mma16816(acc[mf][nf], ah[mf], bfr[nf]);
        }
        __syncthreads();
        if (kt + NSTAGE < nkt) issue_stage(kt + NSTAGE, st);
        else CP_COMMIT();
    }

    // epilogue
    #pragma unroll
    for (int mf = 0; mf < 2; mf++) {
        int r0 = row0 + wm + mf * 16 + (lane >> 2);
        #pragma unroll
        for (int nf = 0; nf < 8; nf++) {
            int cc = col0 + wn + nf * 8 + (lane & 3) * 2;
            if (r0 < M)
                *(float2*)(C + (size_t)r0 * Nn + cc) =
                    make_float2(acc[mf][nf][0], acc[mf][nf][1]);
            if (r0 + 8 < M)
                *(float2*)(C + (size_t)(r0 + 8) * Nn + cc) =
                    make_float2(acc[mf][nf][2], acc[mf][nf][3]);
        }
    }
}

// ------ SpMM (CSR gather) + self loop + bias + ReLU; writes fp16 (+fp32 opt) ----
__global__ void spmm_relu_kernel(const float* __restrict__ h,
                                 const float* __restrict__ bias,
                                 __half* __restrict__ out16,
                                 float* __restrict__ out32,
                                 int C, int write32) {
    int i = blockIdx.x;
    int c = blockIdx.y * blockDim.x + threadIdx.x;
    if (c >= C) return;
    float di = d_dinv[i];
    float acc = di * di * h[i * C + c];
    int e0 = d_rowptr[i], e1 = d_rowptr[i + 1];
    for (int e = e0; e < e1; e++)
        acc += d_eval[e] * h[d_colidx[e] * C + c];
    acc += bias[c];
    acc = acc > 0.0f ? acc : 0.0f;
    out16[i * C + c] = __float2half(acc);
    if (write32) out32[i * C + c] = acc;
}

// ---------------- pooling -------------------------------------------------------
#define POOL_CHUNK 64
__global__ void pool_kernel(const float* __restrict__ h,
                            const int* __restrict__ batch) {
    int c = blockIdx.y * blockDim.x + threadIdx.x;
    int i0 = blockIdx.x * POOL_CHUNK;
    int iend = min(i0 + POOL_CHUNK, N_NODES);
    if (i0 >= N_NODES) return;
    float acc = 0.0f;
    int cur = batch[i0];
    for (int i = i0; i < iend; i++) {
        int b = batch[i];
        if (b != cur) { atomicAdd(&d_pool[cur * C3 + c], acc); acc = 0.0f; cur = b; }
        acc += h[i * C3 + c];
    }
    atomicAdd(&d_pool[cur * C3 + c], acc);
}
__global__ void mean_kernel() {
    int i = blockIdx.x * blockDim.x + threadIdx.x;
    if (i < NUM_GRAPHS * C3) d_pool[i] /= fmaxf(d_gcnt[i / C3], 1.0f);
}

// ---------------- small MLP -----------------------------------------------------
__global__ void mlp_kernel(const float* __restrict__ in,
                           const float* __restrict__ W,
                           const float* __restrict__ bias,
                           float* __restrict__ out,
                           int K, int Mo, int do_relu) {
    __shared__ float sin[1024];
    int row = blockIdx.y;
    for (int k = threadIdx.x; k < K; k += blockDim.x) sin[k] = in[row * K + k];
    __syncthreads();
    int col = blockIdx.x * blockDim.x + threadIdx.x;
    if (col < Mo) {
        float acc = bias[col];
        for (int k = 0; k < K; k++) acc = fmaf(sin[k], W[k * Mo + col], acc);
        if (do_relu) acc = acc > 0.0f ? acc : 0.0f;
        out[row * Mo + col] = acc;
    }
}

// ---------------- launch --------------------------------------------------------
extern "C" void kernel_launch(void* const* d_in, const int* in_sizes, int n_in,
                              void* d_out, int out_size) {
    const int*   type_ids = (const int*)  d_in[0];
    const float* other    = (const float*)d_in[1];
    const int*   eidx     = (const int*)  d_in[2];
    const int*   batch    = (const int*)  d_in[3];
    const float* emb      = (const float*)d_in[4];
    const float* W1 = (const float*)d_in[5];  const float* b1 = (const float*)d_in[6];
    const float* W2 = (const float*)d_in[7];  const float* b2 = (const float*)d_in[8];
    const float* W3 = (const float*)d_in[9];  const float* b3 = (const float*)d_in[10];
    const float* h1w = (const float*)d_in[11]; const float* h1b = (const float*)d_in[12];
    const float* h2w = (const float*)d_in[13]; const float* h2b = (const float*)d_in[14];
    const float* h3w = (const float*)d_in[15]; const float* h3b = (const float*)d_in[16];
    const float* ow  = (const float*)d_in[17]; const float* ob  = (const float*)d_in[18];
    float* out = (float*)d_out;

    float* h_p;    cudaGetSymbolAddress((void**)&h_p,   d_h);
    float* agg_p;  cudaGetSymbolAddress((void**)&agg_p, d_agg);
    float* pool_p; cudaGetSymbolAddress((void**)&pool_p, d_pool);
    float* m1_p;   cudaGetSymbolAddress((void**)&m1_p,  d_m1);
    float* m2_p;   cudaGetSymbolAddress((void**)&m2_p,  d_m2);
    float* m3_p;   cudaGetSymbolAddress((void**)&m3_p,  d_m3);
    __half* a16_p; cudaGetSymbolAddress((void**)&a16_p, d_a16);
    __half* wt_p;  cudaGetSymbolAddress((void**)&wt_p,  d_wt16);

    static int smem_set = 0;
    if (!smem_set) {
        cudaFuncSetAttribute(mma_gemm_kernel,
                             cudaFuncAttributeMaxDynamicSharedMemorySize,
                             NSTAGE * STAGE_BYTES);
        smem_set = 1;
    }

    // graph structure
    init_kernel<<<128, 256>>>();
    count_kernel<<<(N_EDGES + 255) / 256, 256>>>(eidx);
    dinv_kernel<<<(N_NODES + 255) / 256, 256>>>();
    scan_kernel<<<1, 1024>>>();
    fill_kernel<<<(N_EDGES + 255) / 256, 256>>>(eidx);
    gcnt_kernel<<<(N_NODES + 255) / 256, 256>>>(batch);
    embed_kernel<<<N_NODES, K1PAD>>>(type_ids, other, emb);

    const int MT = (N_NODES + BM - 1) / BM;  // 79

    // --- layer 1: [N,192] @ W1t -> h [N,2048] ---
    {
        dim3 tg(K1PAD / 32, C1 / 32);
        tconv_w_kernel<<<tg, dim3(32, 32)>>>(W1, IN_GNN, K1PAD, C1);
        dim3 grid(C1 / BN, MT);
        mma_gemm_kernel<<<grid, 256, NSTAGE * STAGE_BYTES>>>(a16_p, wt_p, h_p,
                                                             N_NODES, C1, K1PAD);
        dim3 sg(N_NODES, C1 / 256);
        spmm_relu_kernel<<<sg, 256>>>(h_p, b1, a16_p, agg_p, C1, 0);
    }
    // --- layer 2: [N,2048] @ W2t -> h [N,1024] ---
    {
        dim3 tg(C1 / 32, C2 / 32);
        tconv_w_kernel<<<tg, dim3(32, 32)>>>(W2, C1, C1, C2);
        dim3 grid(C2 / BN, MT);
        mma_gemm_kernel<<<grid, 256, NSTAGE * STAGE_BYTES>>>(a16_p, wt_p, h_p,
                                                             N_NODES, C2, C1);
        dim3 sg(N_NODES, C2 / 256);
        spmm_relu_kernel<<<sg, 256>>>(h_p, b2, a16_p, agg_p, C2, 0);
    }
    // --- layer 3: [N,1024] @ W3t -> h [N,1024] ---
    {
        dim3 tg(C2 / 32, C3 / 32);
        tconv_w_kernel<<<tg, dim3(32, 32)>>>(W3, C2, C2, C3);
        dim3 grid(C3 / BN, MT);
        mma_gemm_kernel<<<grid, 256, NSTAGE * STAGE_BYTES>>>(a16_p, wt_p, h_p,
                                                             N_NODES, C3, C2);
        dim3 sg(N_NODES, C3 / 256);
        spmm_relu_kernel<<<sg, 256>>>(h_p, b3, a16_p, agg_p, C3, 1);
    }

    // pool + head
    {
        dim3 grid((N_NODES + POOL_CHUNK - 1) / POOL_CHUNK, C3 / 256);
        pool_kernel<<<grid, 256>>>(agg_p, batch);
        mean_kernel<<<(NUM_GRAPHS * C3 + 255) / 256, 256>>>();
        dim3 g1(1024 / 256, NUM_GRAPHS);
        mlp_kernel<<<g1, 256>>>(pool_p, h1w, h1b, m1_p, 1024, 1024, 1);
        mlp_kernel<<<g1, 256>>>(m1_p, h2w, h2b, m2_p, 1024, 1024, 1);
        dim3 g3(H3 / 256, NUM_GRAPHS);
        mlp_kernel<<<g3, 256>>>(m2_p, h3w, h3b, m3_p, 1024, H3, 1);
        dim3 g4(1, NUM_GRAPHS);
        mlp_kernel<<<g4, 256>>>(m3_p, ow, ob, out, H3, NUM_CLASSES, 0);
    }
}

// round 6
// speedup vs baseline: 3.8760x; 1.1430x over previous
#include <cuda_runtime.h>
#include <cuda_fp16.h>
#include <math.h>
#include <stdint.h>

#define N_NODES 10000
#define N_EDGES 80000
#define EMB_DIM 128
#define IN_CH 64
#define IN_GNN 191
#define K1PAD 192
#define C1 2048
#define C2 1024
#define C3 1024
#define NUM_GRAPHS 16
#define H3 512
#define NUM_CLASSES 2

// ---------------- scratch (device globals) ------------------------------------
__device__ __half d_h16[N_NODES * C1];           // GEMM output (fp16)
__device__ __half d_a16[N_NODES * C1];           // fp16 activations (GEMM A input)
__device__ __half d_wt16[C1 * C1];               // W^T fp16 [Nn, Kpad]
__device__ float  d_dinv[N_NODES];
__device__ int    d_cnt[N_NODES];
__device__ int    d_rowptr[N_NODES + 1];
__device__ int    d_wofs[N_NODES];
__device__ int    d_colidx[N_EDGES];
__device__ float  d_eval[N_EDGES];
__device__ float  d_pool[NUM_GRAPHS * C3];
__device__ float  d_gcnt[NUM_GRAPHS];
__device__ float  d_m1[NUM_GRAPHS * 1024];
__device__ float  d_m2[NUM_GRAPHS * 1024];
__device__ float  d_m3[NUM_GRAPHS * H3];

// ---------------- helpers -------------------------------------------------------
__device__ __forceinline__ uint32_t smem_u32(const void* p) {
    uint32_t a;
    asm("{ .reg .u64 t; cvta.to.shared.u64 t, %1; cvt.u32.u64 %0, t; }"
        : "=r"(a) : "l"(p));
    return a;
}
__device__ __forceinline__ void cp16(uint32_t dst, const void* src, bool pred) {
    int sz = pred ? 16 : 0;
    asm volatile("cp.async.cg.shared.global [%0], [%1], 16, %2;"
                 :: "r"(dst), "l"(src), "r"(sz) : "memory");
}
#define CP_COMMIT() asm volatile("cp.async.commit_group;" ::: "memory")
#define CP_WAIT3()  asm volatile("cp.async.wait_group 3;" ::: "memory")

__device__ __forceinline__ void ldsm4(uint32_t (&r)[4], uint32_t a) {
    asm volatile("ldmatrix.sync.aligned.m8n8.x4.shared.b16 {%0,%1,%2,%3}, [%4];"
        : "=r"(r[0]), "=r"(r[1]), "=r"(r[2]), "=r"(r[3]) : "r"(a));
}
__device__ __forceinline__ void mma16816(float (&d)[4], const uint32_t (&a)[4],
                                         const uint32_t* b) {
    asm volatile("mma.sync.aligned.m16n8k16.row.col.f32.f16.f16.f32 "
        "{%0,%1,%2,%3}, {%4,%5,%6,%7}, {%8,%9}, {%0,%1,%2,%3};"
        : "+f"(d[0]), "+f"(d[1]), "+f"(d[2]), "+f"(d[3])
        : "r"(a[0]), "r"(a[1]), "r"(a[2]), "r"(a[3]), "r"(b[0]), "r"(b[1]));
}

// ---------------- setup kernels -------------------------------------------------
__global__ void init_kernel() {
    int i = blockIdx.x * blockDim.x + threadIdx.x;
    int total = N_NODES + NUM_GRAPHS * C3 + NUM_GRAPHS;
    for (; i < total; i += gridDim.x * blockDim.x) {
        if (i < N_NODES) d_cnt[i] = 0;
        else if (i < N_NODES + NUM_GRAPHS * C3) d_pool[i - N_NODES] = 0.0f;
        else d_gcnt[i - N_NODES - NUM_GRAPHS * C3] = 0.0f;
    }
}
__global__ void count_kernel(const int* __restrict__ ei) {
    int e = blockIdx.x * blockDim.x + threadIdx.x;
    if (e < N_EDGES) atomicAdd(&d_cnt[ei[N_EDGES + e]], 1);
}
__global__ void dinv_kernel() {
    int i = blockIdx.x * blockDim.x + threadIdx.x;
    if (i < N_NODES) d_dinv[i] = rsqrtf((float)(d_cnt[i] + 1));
}
__global__ void scan_kernel() {
    __shared__ int ps[1024];
    const int CH = (N_NODES + 1023) / 1024;
    int tid = threadIdx.x, base = tid * CH, s = 0;
    for (int k = 0; k < CH; k++) { int i = base + k; if (i < N_NODES) s += d_cnt[i]; }
    ps[tid] = s; __syncthreads();
    for (int off = 1; off < 1024; off <<= 1) {
        int v = (tid >= off) ? ps[tid - off] : 0;
        __syncthreads(); ps[tid] += v; __syncthreads();
    }
    int run = ps[tid] - s;
    for (int k = 0; k < CH; k++) {
        int i = base + k;
        if (i < N_NODES) { d_rowptr[i] = run; d_wofs[i] = run; run += d_cnt[i]; }
    }
    if (tid == 1023) d_rowptr[N_NODES] = ps[1023];
}
__global__ void fill_kernel(const int* __restrict__ ei) {
    int e = blockIdx.x * blockDim.x + threadIdx.x;
    if (e < N_EDGES) {
        int src = ei[e], dst = ei[N_EDGES + e];
        int pos = atomicAdd(&d_wofs[dst], 1);
        d_colidx[pos] = src;
        d_eval[pos] = d_dinv[src] * d_dinv[dst];
    }
}
// embed + concat straight to fp16 A (padded to K1PAD)
__global__ void embed_kernel(const int* __restrict__ tids,
                             const float* __restrict__ other,
                             const float* __restrict__ emb) {
    int i = blockIdx.x, c = threadIdx.x;  // c in [0, K1PAD)
    float v = 0.0f;
    if (c < EMB_DIM) v = emb[tids[i] * EMB_DIM + c];
    else if (c < IN_GNN) v = other[i * (IN_CH - 1) + (c - EMB_DIM)];
    d_a16[i * K1PAD + c] = __float2half(v);
}
__global__ void gcnt_kernel(const int* __restrict__ batch) {
    int i = blockIdx.x * blockDim.x + threadIdx.x;
    if (i < N_NODES) atomicAdd(&d_gcnt[batch[i]], 1.0f);
}

// W [Kin, Nn] fp32 -> Wt fp16 [Nn, Kpad]
__global__ void tconv_w_kernel(const float* __restrict__ W, int Kin, int Kpad, int Nn) {
    __shared__ float t[32][33];
    int k0 = blockIdx.x * 32, n0 = blockIdx.y * 32;
    int tx = threadIdx.x, ty = threadIdx.y;
    int k = k0 + ty, n = n0 + tx;
    t[ty][tx] = (k < Kin) ? W[(long)k * Nn + n] : 0.0f;
    __syncthreads();
    int nw = n0 + ty, kw = k0 + tx;
    d_wt16[(long)nw * Kpad + kw] = __float2half(t[tx][ty]);
}

// ---------------- mma.sync fp16 GEMM --------------------------------------------
// C16[M,Nn] = A[M,Kp] @ Wt[Nn,Kp]^T, fp32 accum, fp16 output.
#define BM 128
#define BN 128
#define BK 32
#define TILE_BYTES (128 * 32 * 2)      // 8 KB per tile
#define STAGE_BYTES (2 * TILE_BYTES)   // 16 KB (A, B)
#define NSTAGE 4

__global__ __launch_bounds__(256) void mma_gemm_kernel(
    const __half* __restrict__ A, const __half* __restrict__ B,
    __half* __restrict__ C16, int M, int Nn, int Kp) {
    extern __shared__ char smem[];
    uint32_t sbase = smem_u32(smem);
    int tid = threadIdx.x;
    int row0 = blockIdx.y * BM, col0 = blockIdx.x * BN;
    int nkt = Kp / BK;

    int w = tid >> 5, lane = tid & 31;
    int wm = (w & 3) * 32;   // 4 warps along M
    int wn = (w >> 2) * 64;  // 2 warps along N
    int q = lane >> 3, rr = lane & 7;

    float acc[2][8][4] = {};

    auto issue_stage = [&](int kt, int slot) {
        int k0 = kt * BK;
        #pragma unroll
        for (int i = 0; i < 4; i++) {
            int idx = tid + i * 256;
            int t = idx >> 9;
            int r = (idx >> 2) & 127;
            int c = idx & 3;
            int grow = ((t == 0) ? row0 : col0) + r;
            bool ok = (t == 1) || (grow < M);
            const __half* s = (t == 0) ? A : B;
            const char* gp = (const char*)(s + (size_t)(ok ? grow : 0) * Kp + k0) + c * 16;
            uint32_t so = sbase + slot * STAGE_BYTES + t * TILE_BYTES
                        + r * 64 + ((c ^ ((r >> 1) & 3)) << 4);
            cp16(so, gp, ok);
        }
        CP_COMMIT();
    };

    #pragma unroll
    for (int s = 0; s < NSTAGE; s++) {
        if (s < nkt) issue_stage(s, s); else CP_COMMIT();
    }

    for (int kt = 0; kt < nkt; kt++) {
        CP_WAIT3();
        __syncthreads();
        int st = kt & 3;
        uint32_t abase = sbase + st * STAGE_BYTES;
        uint32_t bbase = abase + TILE_BYTES;
        #pragma unroll
        for (int ks = 0; ks < 2; ks++) {
            uint32_t ah[2][4];
            #pragma unroll
            for (int mf = 0; mf < 2; mf++) {
                int row = wm + mf * 16 + (q & 1) * 8 + rr;
                int c = 2 * ks + (q >> 1);
                uint32_t off = row * 64 + ((c ^ ((row >> 1) & 3)) << 4);
                ldsm4(ah[mf], abase + off);
            }
            uint32_t bfr[8][2];
            #pragma unroll
            for (int nf2 = 0; nf2 < 4; nf2++) {
                int n = wn + nf2 * 16 + (q >> 1) * 8 + rr;
                int c = 2 * ks + (q & 1);
                uint32_t off = n * 64 + ((c ^ ((n >> 1) & 3)) << 4);
                uint32_t t0[4];
                ldsm4(t0, bbase + off);
                bfr[2*nf2][0] = t0[0]; bfr[2*nf2][1] = t0[1];
                bfr[2*nf2+1][0] = t0[2]; bfr[2*nf2+1][1] = t0[3];
            }
            #pragma unroll
            for (int mf = 0; mf < 2; mf++)
                #pragma unroll
                for (int nf = 0; nf < 8; nf++)
                    mma16816(acc[mf][nf], ah[mf], bfr[nf]);
        }
        __syncthreads();
        if (kt + NSTAGE < nkt) issue_stage(kt + NSTAGE, st);
        else CP_COMMIT();
    }

    // epilogue: fp16 output
    #pragma unroll
    for (int mf = 0; mf < 2; mf++) {
        int r0 = row0 + wm + mf * 16 + (lane >> 2);
        #pragma unroll
        for (int nf = 0; nf < 8; nf++) {
            int cc = col0 + wn + nf * 8 + (lane & 3) * 2;
            if (r0 < M)
                *(__half2*)(C16 + (size_t)r0 * Nn + cc) =
                    __floats2half2_rn(acc[mf][nf][0], acc[mf][nf][1]);
            if (r0 + 8 < M)
                *(__half2*)(C16 + (size_t)(r0 + 8) * Nn + cc) =
                    __floats2half2_rn(acc[mf][nf][2], acc[mf][nf][3]);
        }
    }
}

// ------ SpMM (CSR gather, fp16 in/out, fp32 accum) + self loop + bias + ReLU ----
__global__ void spmm_relu_kernel(const __half* __restrict__ h16,
                                 const float* __restrict__ bias,
                                 __half* __restrict__ out16, int Cch) {
    int i = blockIdx.x;
    int ch2 = blockIdx.y * blockDim.x + threadIdx.x;   // half2 channel index
    int nch2 = Cch >> 1;
    if (ch2 >= nch2) return;
    const __half2* h2 = (const __half2*)h16;
    float di = d_dinv[i];
    float w0 = di * di;
    float2 sv = __half22float2(h2[(size_t)i * nch2 + ch2]);
    float accx = w0 * sv.x, accy = w0 * sv.y;
    int e0 = d_rowptr[i], e1 = d_rowptr[i + 1];
    for (int e = e0; e < e1; e++) {
        float wv = d_eval[e];
        float2 v = __half22float2(h2[(size_t)d_colidx[e] * nch2 + ch2]);
        accx = fmaf(wv, v.x, accx);
        accy = fmaf(wv, v.y, accy);
    }
    accx += bias[2 * ch2];
    accy += bias[2 * ch2 + 1];
    accx = accx > 0.0f ? accx : 0.0f;
    accy = accy > 0.0f ? accy : 0.0f;
    ((__half2*)out16)[(size_t)i * nch2 + ch2] = __floats2half2_rn(accx, accy);
}

// ---------------- pooling (reads fp16 activations) -----------------------------
#define POOL_CHUNK 64
__global__ void pool_kernel(const __half* __restrict__ h16,
                            const int* __restrict__ batch) {
    int c = blockIdx.y * blockDim.x + threadIdx.x;   // channel
    int i0 = blockIdx.x * POOL_CHUNK;
    int iend = min(i0 + POOL_CHUNK, N_NODES);
    if (i0 >= N_NODES) return;
    float acc = 0.0f;
    int cur = batch[i0];
    for (int i = i0; i < iend; i++) {
        int b = batch[i];
        if (b != cur) { atomicAdd(&d_pool[cur * C3 + c], acc); acc = 0.0f; cur = b; }
        acc += __half2float(h16[(size_t)i * C3 + c]);
    }
    atomicAdd(&d_pool[cur * C3 + c], acc);
}
__global__ void mean_kernel() {
    int i = blockIdx.x * blockDim.x + threadIdx.x;
    if (i < NUM_GRAPHS * C3) d_pool[i] /= fmaxf(d_gcnt[i / C3], 1.0f);
}

// ---------------- small MLP -----------------------------------------------------
__global__ void mlp_kernel(const float* __restrict__ in,
                           const float* __restrict__ W,
                           const float* __restrict__ bias,
                           float* __restrict__ out,
                           int K, int Mo, int do_relu) {
    __shared__ float sin[1024];
    int row = blockIdx.y;
    for (int k = threadIdx.x; k < K; k += blockDim.x) sin[k] = in[row * K + k];
    __syncthreads();
    int col = blockIdx.x * blockDim.x + threadIdx.x;
    if (col < Mo) {
        float acc = bias[col];
        for (int k = 0; k < K; k++) acc = fmaf(sin[k], W[k * Mo + col], acc);
        if (do_relu) acc = acc > 0.0f ? acc : 0.0f;
        out[row * Mo + col] = acc;
    }
}

// ---------------- launch --------------------------------------------------------
extern "C" void kernel_launch(void* const* d_in, const int* in_sizes, int n_in,
                              void* d_out, int out_size) {
    const int*   type_ids = (const int*)  d_in[0];
    const float* other    = (const float*)d_in[1];
    const int*   eidx     = (const int*)  d_in[2];
    const int*   batch    = (const int*)  d_in[3];
    const float* emb      = (const float*)d_in[4];
    const float* W1 = (const float*)d_in[5];  const float* b1 = (const float*)d_in[6];
    const float* W2 = (const float*)d_in[7];  const float* b2 = (const float*)d_in[8];
    const float* W3 = (const float*)d_in[9];  const float* b3 = (const float*)d_in[10];
    const float* h1w = (const float*)d_in[11]; const float* h1b = (const float*)d_in[12];
    const float* h2w = (const float*)d_in[13]; const float* h2b = (const float*)d_in[14];
    const float* h3w = (const float*)d_in[15]; const float* h3b = (const float*)d_in[16];
    const float* ow  = (const float*)d_in[17]; const float* ob  = (const float*)d_in[18];
    float* out = (float*)d_out;

    float* pool_p; cudaGetSymbolAddress((void**)&pool_p, d_pool);
    float* m1_p;   cudaGetSymbolAddress((void**)&m1_p,  d_m1);
    float* m2_p;   cudaGetSymbolAddress((void**)&m2_p,  d_m2);
    float* m3_p;   cudaGetSymbolAddress((void**)&m3_p,  d_m3);
    __half* h16_p; cudaGetSymbolAddress((void**)&h16_p, d_h16);
    __half* a16_p; cudaGetSymbolAddress((void**)&a16_p, d_a16);
    __half* wt_p;  cudaGetSymbolAddress((void**)&wt_p,  d_wt16);

    static int smem_set = 0;
    if (!smem_set) {
        cudaFuncSetAttribute(mma_gemm_kernel,
                             cudaFuncAttributeMaxDynamicSharedMemorySize,
                             NSTAGE * STAGE_BYTES);
        smem_set = 1;
    }

    // graph structure
    init_kernel<<<128, 256>>>();
    count_kernel<<<(N_EDGES + 255) / 256, 256>>>(eidx);
    dinv_kernel<<<(N_NODES + 255) / 256, 256>>>();
    scan_kernel<<<1, 1024>>>();
    fill_kernel<<<(N_EDGES + 255) / 256, 256>>>(eidx);
    gcnt_kernel<<<(N_NODES + 255) / 256, 256>>>(batch);
    embed_kernel<<<N_NODES, K1PAD>>>(type_ids, other, emb);

    const int MT = (N_NODES + BM - 1) / BM;  // 79

    // --- layer 1: [N,192] @ W1t -> h [N,2048] ---
    {
        dim3 tg(K1PAD / 32, C1 / 32);
        tconv_w_kernel<<<tg, dim3(32, 32)>>>(W1, IN_GNN, K1PAD, C1);
        dim3 grid(C1 / BN, MT);
        mma_gemm_kernel<<<grid, 256, NSTAGE * STAGE_BYTES>>>(a16_p, wt_p, h16_p,
                                                             N_NODES, C1, K1PAD);
        dim3 sg(N_NODES, (C1 / 2) / 256);
        spmm_relu_kernel<<<sg, 256>>>(h16_p, b1, a16_p, C1);
    }
    // --- layer 2: [N,2048] @ W2t -> h [N,1024] ---
    {
        dim3 tg(C1 / 32, C2 / 32);
        tconv_w_kernel<<<tg, dim3(32, 32)>>>(W2, C1, C1, C2);
        dim3 grid(C2 / BN, MT);
        mma_gemm_kernel<<<grid, 256, NSTAGE * STAGE_BYTES>>>(a16_p, wt_p, h16_p,
                                                             N_NODES, C2, C1);
        dim3 sg(N_NODES, (C2 / 2) / 256);
        spmm_relu_kernel<<<sg, 256>>>(h16_p, b2, a16_p, C2);
    }
    // --- layer 3: [N,1024] @ W3t -> h [N,1024] ---
    {
        dim3 tg(C2 / 32, C3 / 32);
        tconv_w_kernel<<<tg, dim3(32, 32)>>>(W3, C2, C2, C3);
        dim3 grid(C3 / BN, MT);
        mma_gemm_kernel<<<grid, 256, NSTAGE * STAGE_BYTES>>>(a16_p, wt_p, h16_p,
                                                             N_NODES, C3, C2);
        dim3 sg(N_NODES, (C3 / 2) / 256);
        spmm_relu_kernel<<<sg, 256>>>(h16_p, b3, a16_p, C3);
    }

    // pool + head
    {
        dim3 grid((N_NODES + POOL_CHUNK - 1) / POOL_CHUNK, C3 / 256);
        pool_kernel<<<grid, 256>>>(a16_p, batch);
        mean_kernel<<<(NUM_GRAPHS * C3 + 255) / 256, 256>>>();
        dim3 g1(1024 / 256, NUM_GRAPHS);
        mlp_kernel<<<g1, 256>>>(pool_p, h1w, h1b, m1_p, 1024, 1024, 1);
        mlp_kernel<<<g1, 256>>>(m1_p, h2w, h2b, m2_p, 1024, 1024, 1);
        dim3 g3(H3 / 256, NUM_GRAPHS);
        mlp_kernel<<<g3, 256>>>(m2_p, h3w, h3b, m3_p, 1024, H3, 1);
        dim3 g4(1, NUM_GRAPHS);
        mlp_kernel<<<g4, 256>>>(m3_p, ow, ob, out, H3, NUM_CLASSES, 0);
    }
}

// round 7
// speedup vs baseline: 4.2962x; 1.1084x over previous
#include <cuda_runtime.h>
#include <cuda_fp16.h>
#include <math.h>
#include <stdint.h>

#define N_NODES 10000
#define N_EDGES 80000
#define EMB_DIM 128
#define IN_CH 64
#define IN_GNN 191
#define K1PAD 192
#define C1 2048
#define C2 1024
#define C3 1024
#define NUM_GRAPHS 16
#define H3 512
#define NUM_CLASSES 2

// ---------------- scratch (device globals) ------------------------------------
__device__ __half d_h16[N_NODES * C1];           // GEMM output (fp16)
__device__ __half d_a16[N_NODES * C1];           // fp16 activations (GEMM A input)
__device__ __half d_wt16[C1 * C1];               // W^T fp16 [Nn, Kpad]
__device__ float  d_dinv[N_NODES];
__device__ int    d_cnt[N_NODES];
__device__ int    d_rowptr[N_NODES + 1];
__device__ int    d_wofs[N_NODES];
__device__ int    d_colidx[N_EDGES];
__device__ float  d_eval[N_EDGES];
__device__ float  d_pool[NUM_GRAPHS * C3];
__device__ float  d_gcnt[NUM_GRAPHS];
__device__ float  d_m1[NUM_GRAPHS * 1024];
__device__ float  d_m2[NUM_GRAPHS * 1024];
__device__ float  d_m3[NUM_GRAPHS * H3];

// ---------------- helpers -------------------------------------------------------
__device__ __forceinline__ uint32_t smem_u32(const void* p) {
    uint32_t a;
    asm("{ .reg .u64 t; cvta.to.shared.u64 t, %1; cvt.u32.u64 %0, t; }"
        : "=r"(a) : "l"(p));
    return a;
}
__device__ __forceinline__ void cp16(uint32_t dst, const void* src, bool pred) {
    int sz = pred ? 16 : 0;
    asm volatile("cp.async.cg.shared.global [%0], [%1], 16, %2;"
                 :: "r"(dst), "l"(src), "r"(sz) : "memory");
}
#define CP_COMMIT() asm volatile("cp.async.commit_group;" ::: "memory")
#define CP_WAIT3()  asm volatile("cp.async.wait_group 3;" ::: "memory")

__device__ __forceinline__ void ldsm4(uint32_t (&r)[4], uint32_t a) {
    asm volatile("ldmatrix.sync.aligned.m8n8.x4.shared.b16 {%0,%1,%2,%3}, [%4];"
        : "=r"(r[0]), "=r"(r[1]), "=r"(r[2]), "=r"(r[3]) : "r"(a));
}
__device__ __forceinline__ void mma16816(float (&d)[4], const uint32_t (&a)[4],
                                         const uint32_t* b) {
    asm volatile("mma.sync.aligned.m16n8k16.row.col.f32.f16.f16.f32 "
        "{%0,%1,%2,%3}, {%4,%5,%6,%7}, {%8,%9}, {%0,%1,%2,%3};"
        : "+f"(d[0]), "+f"(d[1]), "+f"(d[2]), "+f"(d[3])
        : "r"(a[0]), "r"(a[1]), "r"(a[2]), "r"(a[3]), "r"(b[0]), "r"(b[1]));
}

// ---------------- setup kernels -------------------------------------------------
__global__ void init_kernel() {
    int i = blockIdx.x * blockDim.x + threadIdx.x;
    int total = N_NODES + NUM_GRAPHS * C3 + NUM_GRAPHS;
    for (; i < total; i += gridDim.x * blockDim.x) {
        if (i < N_NODES) d_cnt[i] = 0;
        else if (i < N_NODES + NUM_GRAPHS * C3) d_pool[i - N_NODES] = 0.0f;
        else d_gcnt[i - N_NODES - NUM_GRAPHS * C3] = 0.0f;
    }
}
// fused: edge in-degree count + per-graph node count
__global__ void count_kernel(const int* __restrict__ ei,
                             const int* __restrict__ batch) {
    int idx = blockIdx.x * blockDim.x + threadIdx.x;
    if (idx < N_EDGES) atomicAdd(&d_cnt[ei[N_EDGES + idx]], 1);
    if (idx < N_NODES) atomicAdd(&d_gcnt[batch[idx]], 1.0f);
}
// fused: exclusive scan of counts + dinv
__global__ void scan_kernel() {
    __shared__ int ps[1024];
    const int CH = (N_NODES + 1023) / 1024;
    int tid = threadIdx.x, base = tid * CH, s = 0;
    for (int k = 0; k < CH; k++) { int i = base + k; if (i < N_NODES) s += d_cnt[i]; }
    ps[tid] = s; __syncthreads();
    for (int off = 1; off < 1024; off <<= 1) {
        int v = (tid >= off) ? ps[tid - off] : 0;
        __syncthreads(); ps[tid] += v; __syncthreads();
    }
    int run = ps[tid] - s;
    for (int k = 0; k < CH; k++) {
        int i = base + k;
        if (i < N_NODES) {
            d_rowptr[i] = run; d_wofs[i] = run; run += d_cnt[i];
            d_dinv[i] = rsqrtf((float)(d_cnt[i] + 1));
        }
    }
    if (tid == 1023) d_rowptr[N_NODES] = ps[1023];
}
__global__ void fill_kernel(const int* __restrict__ ei) {
    int e = blockIdx.x * blockDim.x + threadIdx.x;
    if (e < N_EDGES) {
        int src = ei[e], dst = ei[N_EDGES + e];
        int pos = atomicAdd(&d_wofs[dst], 1);
        d_colidx[pos] = src;
        d_eval[pos] = d_dinv[src] * d_dinv[dst];
    }
}
// embed + concat straight to fp16 A (padded to K1PAD)
__global__ void embed_kernel(const int* __restrict__ tids,
                             const float* __restrict__ other,
                             const float* __restrict__ emb) {
    int i = blockIdx.x, c = threadIdx.x;  // c in [0, K1PAD)
    float v = 0.0f;
    if (c < EMB_DIM) v = emb[tids[i] * EMB_DIM + c];
    else if (c < IN_GNN) v = other[i * (IN_CH - 1) + (c - EMB_DIM)];
    d_a16[i * K1PAD + c] = __float2half(v);
}

// W [Kin, Nn] fp32 -> Wt fp16 [Nn, Kpad]
__global__ void tconv_w_kernel(const float* __restrict__ W, int Kin, int Kpad, int Nn) {
    __shared__ float t[32][33];
    int k0 = blockIdx.x * 32, n0 = blockIdx.y * 32;
    int tx = threadIdx.x, ty = threadIdx.y;
    int k = k0 + ty, n = n0 + tx;
    t[ty][tx] = (k < Kin) ? W[(long)k * Nn + n] : 0.0f;
    __syncthreads();
    int nw = n0 + ty, kw = k0 + tx;
    d_wt16[(long)nw * Kpad + kw] = __float2half(t[tx][ty]);
}

// ---------------- mma.sync fp16 GEMM --------------------------------------------
#define BM 128
#define BN 128
#define BK 32
#define TILE_BYTES (128 * 32 * 2)      // 8 KB per tile
#define STAGE_BYTES (2 * TILE_BYTES)   // 16 KB (A, B)
#define NSTAGE 4

__global__ __launch_bounds__(256) void mma_gemm_kernel(
    const __half* __restrict__ A, const __half* __restrict__ B,
    __half* __restrict__ C16, int M, int Nn, int Kp) {
    extern __shared__ char smem[];
    uint32_t sbase = smem_u32(smem);
    int tid = threadIdx.x;
    int row0 = blockIdx.y * BM, col0 = blockIdx.x * BN;
    int nkt = Kp / BK;

    int w = tid >> 5, lane = tid & 31;
    int wm = (w & 3) * 32;   // 4 warps along M
    int wn = (w >> 2) * 64;  // 2 warps along N
    int q = lane >> 3, rr = lane & 7;

    float acc[2][8][4] = {};

    auto issue_stage = [&](int kt, int slot) {
        int k0 = kt * BK;
        #pragma unroll
        for (int i = 0; i < 4; i++) {
            int idx = tid + i * 256;
            int t = idx >> 9;
            int r = (idx >> 2) & 127;
            int c = idx & 3;
            int grow = ((t == 0) ? row0 : col0) + r;
            bool ok = (t == 1) || (grow < M);
            const __half* s = (t == 0) ? A : B;
            const char* gp = (const char*)(s + (size_t)(ok ? grow : 0) * Kp + k0) + c * 16;
            uint32_t so = sbase + slot * STAGE_BYTES + t * TILE_BYTES
                        + r * 64 + ((c ^ ((r >> 1) & 3)) << 4);
            cp16(so, gp, ok);
        }
        CP_COMMIT();
    };

    #pragma unroll
    for (int s = 0; s < NSTAGE; s++) {
        if (s < nkt) issue_stage(s, s); else CP_COMMIT();
    }

    for (int kt = 0; kt < nkt; kt++) {
        CP_WAIT3();
        __syncthreads();
        int st = kt & 3;
        uint32_t abase = sbase + st * STAGE_BYTES;
        uint32_t bbase = abase + TILE_BYTES;
        #pragma unroll
        for (int ks = 0; ks < 2; ks++) {
            uint32_t ah[2][4];
            #pragma unroll
            for (int mf = 0; mf < 2; mf++) {
                int row = wm + mf * 16 + (q & 1) * 8 + rr;
                int c = 2 * ks + (q >> 1);
                uint32_t off = row * 64 + ((c ^ ((row >> 1) & 3)) << 4);
                ldsm4(ah[mf], abase + off);
            }
            uint32_t bfr[8][2];
            #pragma unroll
            for (int nf2 = 0; nf2 < 4; nf2++) {
                int n = wn + nf2 * 16 + (q >> 1) * 8 + rr;
                int c = 2 * ks + (q & 1);
                uint32_t off = n * 64 + ((c ^ ((n >> 1) & 3)) << 4);
                uint32_t t0[4];
                ldsm4(t0, bbase + off);
                bfr[2*nf2][0] = t0[0]; bfr[2*nf2][1] = t0[1];
                bfr[2*nf2+1][0] = t0[2]; bfr[2*nf2+1][1] = t0[3];
            }
            #pragma unroll
            for (int mf = 0; mf < 2; mf++)
                #pragma unroll
                for (int nf = 0; nf < 8; nf++)
                    mma16816(acc[mf][nf], ah[mf], bfr[nf]);
        }
        __syncthreads();
        if (kt + NSTAGE < nkt) issue_stage(kt + NSTAGE, st);
        else CP_COMMIT();
    }

    // epilogue: fp16 output
    #pragma unroll
    for (int mf = 0; mf < 2; mf++) {
        int r0 = row0 + wm + mf * 16 + (lane >> 2);
        #pragma unroll
        for (int nf = 0; nf < 8; nf++) {
            int cc = col0 + wn + nf * 8 + (lane & 3) * 2;
            if (r0 < M)
                *(__half2*)(C16 + (size_t)r0 * Nn + cc) =
                    __floats2half2_rn(acc[mf][nf][0], acc[mf][nf][1]);
            if (r0 + 8 < M)
                *(__half2*)(C16 + (size_t)(r0 + 8) * Nn + cc) =
                    __floats2half2_rn(acc[mf][nf][2], acc[mf][nf][3]);
        }
    }
}

// ------ SpMM (CSR gather, fp16 in/out, fp32 accum, MLP-4 edge loop) -------------
__global__ void spmm_relu_kernel(const __half* __restrict__ h16,
                                 const float* __restrict__ bias,
                                 __half* __restrict__ out16, int Cch) {
    int i = blockIdx.x;
    int ch2 = blockIdx.y * blockDim.x + threadIdx.x;   // half2 channel index
    int nch2 = Cch >> 1;
    if (ch2 >= nch2) return;
    const __half2* h2 = (const __half2*)h16;
    float di = d_dinv[i];
    float w0 = di * di;
    float2 sv = __half22float2(h2[(size_t)i * nch2 + ch2]);
    float accx = w0 * sv.x, accy = w0 * sv.y;
    int e0 = d_rowptr[i], e1 = d_rowptr[i + 1];
    int e = e0;
    for (; e + 4 <= e1; e += 4) {
        int  c0 = d_colidx[e],     c1 = d_colidx[e + 1];
        int  c2v = d_colidx[e + 2], c3v = d_colidx[e + 3];
        float wv0 = d_eval[e],     wv1 = d_eval[e + 1];
        float wv2 = d_eval[e + 2], wv3 = d_eval[e + 3];
        float2 v0 = __half22float2(h2[(size_t)c0  * nch2 + ch2]);
        float2 v1 = __half22float2(h2[(size_t)c1  * nch2 + ch2]);
        float2 v2 = __half22float2(h2[(size_t)c2v * nch2 + ch2]);
        float2 v3 = __half22float2(h2[(size_t)c3v * nch2 + ch2]);
        accx = fmaf(wv0, v0.x, accx); accy = fmaf(wv0, v0.y, accy);
        accx = fmaf(wv1, v1.x, accx); accy = fmaf(wv1, v1.y, accy);
        accx = fmaf(wv2, v2.x, accx); accy = fmaf(wv2, v2.y, accy);
        accx = fmaf(wv3, v3.x, accx); accy = fmaf(wv3, v3.y, accy);
    }
    for (; e < e1; e++) {
        float wv = d_eval[e];
        float2 v = __half22float2(h2[(size_t)d_colidx[e] * nch2 + ch2]);
        accx = fmaf(wv, v.x, accx);
        accy = fmaf(wv, v.y, accy);
    }
    accx += bias[2 * ch2];
    accy += bias[2 * ch2 + 1];
    accx = accx > 0.0f ? accx : 0.0f;
    accy = accy > 0.0f ? accy : 0.0f;
    ((__half2*)out16)[(size_t)i * nch2 + ch2] = __floats2half2_rn(accx, accy);
}

// ---------------- pooling (reads fp16 activations) -----------------------------
#define POOL_CHUNK 64
__global__ void pool_kernel(const __half* __restrict__ h16,
                            const int* __restrict__ batch) {
    int c = blockIdx.y * blockDim.x + threadIdx.x;   // channel
    int i0 = blockIdx.x * POOL_CHUNK;
    int iend = min(i0 + POOL_CHUNK, N_NODES);
    if (i0 >= N_NODES) return;
    float acc = 0.0f;
    int cur = batch[i0];
    for (int i = i0; i < iend; i++) {
        int b = batch[i];
        if (b != cur) { atomicAdd(&d_pool[cur * C3 + c], acc); acc = 0.0f; cur = b; }
        acc += __half2float(h16[(size_t)i * C3 + c]);
    }
    atomicAdd(&d_pool[cur * C3 + c], acc);
}

// ---------------- small MLP (optional mean-divide on input) ---------------------
__global__ void mlp_kernel(const float* __restrict__ in,
                           const float* __restrict__ W,
                           const float* __restrict__ bias,
                           float* __restrict__ out,
                           int K, int Mo, int do_relu, int do_mean) {
    __shared__ float sin[1024];
    int row = blockIdx.y;
    float scale = 1.0f;
    if (do_mean) scale = 1.0f / fmaxf(d_gcnt[row], 1.0f);
    for (int k = threadIdx.x; k < K; k += blockDim.x)
        sin[k] = in[row * K + k] * scale;
    __syncthreads();
    int col = blockIdx.x * blockDim.x + threadIdx.x;
    if (col < Mo) {
        float acc = bias[col];
        for (int k = 0; k < K; k++) acc = fmaf(sin[k], W[k * Mo + col], acc);
        if (do_relu) acc = acc > 0.0f ? acc : 0.0f;
        out[row * Mo + col] = acc;
    }
}

// ---------------- launch --------------------------------------------------------
extern "C" void kernel_launch(void* const* d_in, const int* in_sizes, int n_in,
                              void* d_out, int out_size) {
    const int*   type_ids = (const int*)  d_in[0];
    const float* other    = (const float*)d_in[1];
    const int*   eidx     = (const int*)  d_in[2];
    const int*   batch    = (const int*)  d_in[3];
    const float* emb      = (const float*)d_in[4];
    const float* W1 = (const float*)d_in[5];  const float* b1 = (const float*)d_in[6];
    const float* W2 = (const float*)d_in[7];  const float* b2 = (const float*)d_in[8];
    const float* W3 = (const float*)d_in[9];  const float* b3 = (const float*)d_in[10];
    const float* h1w = (const float*)d_in[11]; const float* h1b = (const float*)d_in[12];
    const float* h2w = (const float*)d_in[13]; const float* h2b = (const float*)d_in[14];
    const float* h3w = (const float*)d_in[15]; const float* h3b = (const float*)d_in[16];
    const float* ow  = (const float*)d_in[17]; const float* ob  = (const float*)d_in[18];
    float* out = (float*)d_out;

    float* pool_p; cudaGetSymbolAddress((void**)&pool_p, d_pool);
    float* m1_p;   cudaGetSymbolAddress((void**)&m1_p,  d_m1);
    float* m2_p;   cudaGetSymbolAddress((void**)&m2_p,  d_m2);
    float* m3_p;   cudaGetSymbolAddress((void**)&m3_p,  d_m3);
    __half* h16_p; cudaGetSymbolAddress((void**)&h16_p, d_h16);
    __half* a16_p; cudaGetSymbolAddress((void**)&a16_p, d_a16);
    __half* wt_p;  cudaGetSymbolAddress((void**)&wt_p,  d_wt16);

    static int smem_set = 0;
    if (!smem_set) {
        cudaFuncSetAttribute(mma_gemm_kernel,
                             cudaFuncAttributeMaxDynamicSharedMemorySize,
                             NSTAGE * STAGE_BYTES);
        smem_set = 1;
    }

    // graph structure
    init_kernel<<<128, 256>>>();
    count_kernel<<<(N_EDGES + 255) / 256, 256>>>(eidx, batch);
    scan_kernel<<<1, 1024>>>();
    fill_kernel<<<(N_EDGES + 255) / 256, 256>>>(eidx);
    embed_kernel<<<N_NODES, K1PAD>>>(type_ids, other, emb);

    const int MT = (N_NODES + BM - 1) / BM;  // 79

    // --- layer 1: [N,192] @ W1t -> h [N,2048] ---
    {
        dim3 tg(K1PAD / 32, C1 / 32);
        tconv_w_kernel<<<tg, dim3(32, 32)>>>(W1, IN_GNN, K1PAD, C1);
        dim3 grid(C1 / BN, MT);
        mma_gemm_kernel<<<grid, 256, NSTAGE * STAGE_BYTES>>>(a16_p, wt_p, h16_p,
                                                             N_NODES, C1, K1PAD);
        dim3 sg(N_NODES, (C1 / 2) / 256);
        spmm_relu_kernel<<<sg, 256>>>(h16_p, b1, a16_p, C1);
    }
    // --- layer 2: [N,2048] @ W2t -> h [N,1024] ---
    {
        dim3 tg(C1 / 32, C2 / 32);
        tconv_w_kernel<<<tg, dim3(32, 32)>>>(W2, C1, C1, C2);
        dim3 grid(C2 / BN, MT);
        mma_gemm_kernel<<<grid, 256, NSTAGE * STAGE_BYTES>>>(a16_p, wt_p, h16_p,
                                                             N_NODES, C2, C1);
        dim3 sg(N_NODES, (C2 / 2) / 256);
        spmm_relu_kernel<<<sg, 256>>>(h16_p, b2, a16_p, C2);
    }
    // --- layer 3: [N,1024] @ W3t -> h [N,1024] ---
    {
        dim3 tg(C2 / 32, C3 / 32);
        tconv_w_kernel<<<tg, dim3(32, 32)>>>(W3, C2, C2, C3);
        dim3 grid(C3 / BN, MT);
        mma_gemm_kernel<<<grid, 256, NSTAGE * STAGE_BYTES>>>(a16_p, wt_p, h16_p,
                                                             N_NODES, C3, C2);
        dim3 sg(N_NODES, (C3 / 2) / 256);
        spmm_relu_kernel<<<sg, 256>>>(h16_p, b3, a16_p, C3);
    }

    // pool + head (mean folded into first MLP layer)
    {
        dim3 grid((N_NODES + POOL_CHUNK - 1) / POOL_CHUNK, C3 / 256);
        pool_kernel<<<grid, 256>>>(a16_p, batch);
        dim3 g1(1024 / 256, NUM_GRAPHS);
        mlp_kernel<<<g1, 256>>>(pool_p, h1w, h1b, m1_p, 1024, 1024, 1, 1);
        mlp_kernel<<<g1, 256>>>(m1_p, h2w, h2b, m2_p, 1024, 1024, 1, 0);
        dim3 g3(H3 / 256, NUM_GRAPHS);
        mlp_kernel<<<g3, 256>>>(m2_p, h3w, h3b, m3_p, 1024, H3, 1, 0);
        dim3 g4(1, NUM_GRAPHS);
        mlp_kernel<<<g4, 256>>>(m3_p, ow, ob, out, H3, NUM_CLASSES, 0, 0);
    }
}